// round 1
// baseline (speedup 1.0000x reference)
#include <cuda_runtime.h>

#define B      8
#define IN_CH  64
#define OUT_CH 64
#define KS     3
#define GROUPS 8
#define FPG    8          // IN_CH / GROUPS, also out-channels per group
#define H      256
#define WD     256
#define TY     16         // output rows per block

// Scratch for the dynamic filter taps: leaky_relu(rep @ W^T), [B, OUT_CH*9]
__device__ float g_wk[B * OUT_CH * KS * KS];

__global__ void prep_weights(const float* __restrict__ rep,
                             const float* __restrict__ Wm) {
    int idx = blockIdx.x * blockDim.x + threadIdx.x;
    if (idx >= B * OUT_CH * KS * KS) return;
    int b  = idx / (OUT_CH * KS * KS);
    int o9 = idx - b * (OUT_CH * KS * KS);
    const float* r = rep + b * 32;
    const float* w = Wm + o9 * 32;
    float acc = 0.f;
#pragma unroll
    for (int i = 0; i < 32; i++) acc = fmaf(r[i], w[i], acc);
    g_wk[idx] = acc >= 0.f ? acc : 0.1f * acc;
}

__global__ __launch_bounds__(256, 2)
void dynconv(const float* __restrict__ x, float* __restrict__ out) {
    __shared__ float S[TY + 2][WD + 2];   // group-sum tile incl. halo
    __shared__ float wk[FPG * 9];         // 72 taps for this (b, g)

    const int tid  = threadIdx.x;
    const int tile = blockIdx.x;          // 0..15
    const int g    = blockIdx.y;          // 0..7
    const int b    = blockIdx.z;          // 0..7
    const int y0   = tile * TY;

    if (tid < FPG * 9)
        wk[tid] = g_wk[b * (OUT_CH * 9) + g * (FPG * 9) + tid];

    const float* xg = x + ((size_t)(b * IN_CH + g * FPG)) * H * WD;

    // Phase 1: reflect-padded load of 8 channels, summed into smem
    for (int idx = tid; idx < (TY + 2) * (WD + 2); idx += 256) {
        int r  = idx / (WD + 2);
        int cc = idx - r * (WD + 2);
        int gy = y0 + r - 1;
        gy = gy < 0 ? -gy : (gy >= H ? 2 * H - 2 - gy : gy);
        int gx = cc - 1;
        gx = gx < 0 ? -gx : (gx >= WD ? 2 * WD - 2 - gx : gx);
        const float* p = xg + gy * WD + gx;
        float s = 0.f;
#pragma unroll
        for (int c = 0; c < FPG; c++) s += p[(size_t)c * H * WD];
        S[r][cc] = s;
    }
    __syncthreads();

    // taps into registers (indices all compile-time constant)
    float wr[FPG * 9];
#pragma unroll
    for (int i = 0; i < FPG * 9; i++) wr[i] = wk[i];

    const int c = tid;                    // one column per thread (0..255)
    float a0 = S[0][c], a1 = S[0][c + 1], a2 = S[0][c + 2];
    float b0 = S[1][c], b1 = S[1][c + 1], b2 = S[1][c + 2];

    float* outp = out + (((size_t)b * OUT_CH + g * FPG) * H + y0) * WD + c;

#pragma unroll 4
    for (int y = 0; y < TY; y++) {
        float c0 = S[y + 2][c], c1 = S[y + 2][c + 1], c2 = S[y + 2][c + 2];
#pragma unroll
        for (int j = 0; j < FPG; j++) {
            float acc;
            acc = wr[j * 9 + 0] * a0;
            acc = fmaf(wr[j * 9 + 1], a1, acc);
            acc = fmaf(wr[j * 9 + 2], a2, acc);
            acc = fmaf(wr[j * 9 + 3], b0, acc);
            acc = fmaf(wr[j * 9 + 4], b1, acc);
            acc = fmaf(wr[j * 9 + 5], b2, acc);
            acc = fmaf(wr[j * 9 + 6], c0, acc);
            acc = fmaf(wr[j * 9 + 7], c1, acc);
            acc = fmaf(wr[j * 9 + 8], c2, acc);
            outp[(size_t)j * H * WD + y * WD] = acc;
        }
        a0 = b0; a1 = b1; a2 = b2;
        b0 = c0; b1 = c1; b2 = c2;
    }
}

extern "C" void kernel_launch(void* const* d_in, const int* in_sizes, int n_in,
                              void* d_out, int out_size) {
    const float* x   = (const float*)d_in[0];  // [8,64,256,256]
    const float* rep = (const float*)d_in[1];  // [8,32]
    const float* Wm  = (const float*)d_in[2];  // [576,32]
    float* out = (float*)d_out;                // [8,64,256,256]

    prep_weights<<<(B * OUT_CH * KS * KS + 127) / 128, 128>>>(rep, Wm);
    dynconv<<<dim3(H / TY, GROUPS, B), 256>>>(x, out);
}

// round 2
// speedup vs baseline: 1.3752x; 1.3752x over previous
#include <cuda_runtime.h>

#define NB     8          // batch
#define IN_CH  64
#define OUT_CH 64
#define KS     3
#define GROUPS 8
#define FPG    8          // channels per group = out-channels per group
#define H      256
#define WD     256
#define TY     16         // output rows per block
#define SW     264        // smem row stride (floats): 264*4 = 1056 = 16*66, keeps float4 STS aligned

// Scratch for dynamic filter taps: leaky_relu(rep @ W^T), [NB, OUT_CH*9]
__device__ float g_wk[NB * OUT_CH * KS * KS];

__global__ void prep_weights(const float* __restrict__ rep,
                             const float* __restrict__ Wm) {
    int idx = blockIdx.x * blockDim.x + threadIdx.x;
    if (idx >= NB * OUT_CH * KS * KS) return;
    int b  = idx / (OUT_CH * KS * KS);
    int o9 = idx - b * (OUT_CH * KS * KS);
    const float* r = rep + b * 32;
    const float* w = Wm + o9 * 32;
    float acc = 0.f;
#pragma unroll
    for (int i = 0; i < 32; i++) acc = fmaf(r[i], w[i], acc);
    g_wk[idx] = acc >= 0.f ? acc : 0.1f * acc;
}

__global__ __launch_bounds__(256)
void dynconv(const float* __restrict__ x, float* __restrict__ out) {
    __shared__ float S[(TY + 2) * SW];    // group-sum tile: halo col L at idx 3, interior 4..259, halo R at 260
    __shared__ float wk[FPG * 9];

    const int tid = threadIdx.x;
    const int y0  = blockIdx.x * TY;
    const int g   = blockIdx.y;
    const int bb  = blockIdx.z;

    if (tid < FPG * 9)
        wk[tid] = g_wk[bb * (OUT_CH * 9) + g * (FPG * 9) + tid];

    const float* xg = x + ((size_t)(bb * IN_CH + g * FPG)) * H * WD;

    // ---- Phase 1a: interior, float4 vectorized. (TY+2) rows x 64 float4 each.
    for (int idx = tid; idx < (TY + 2) * (WD / 4); idx += 256) {
        int r = idx >> 6;          // / 64
        int q = idx & 63;
        int gy = y0 + r - 1;
        gy = gy < 0 ? -gy : (gy >= H ? 2 * H - 2 - gy : gy);
        const float4* p = (const float4*)(xg + (size_t)gy * WD) + q;
        float4 s = p[0];
#pragma unroll
        for (int c = 1; c < FPG; c++) {
            float4 v = p[(size_t)c * (H * WD / 4)];
            s.x += v.x; s.y += v.y; s.z += v.z; s.w += v.w;
        }
        *(float4*)&S[r * SW + 4 + 4 * q] = s;
    }
    // ---- Phase 1b: reflected halo columns (gx=-1 -> 1, gx=256 -> 254)
    if (tid < 2 * (TY + 2)) {
        int r    = tid >> 1;
        int side = tid & 1;
        int gy = y0 + r - 1;
        gy = gy < 0 ? -gy : (gy >= H ? 2 * H - 2 - gy : gy);
        int gx = side ? (WD - 2) : 1;
        const float* p = xg + (size_t)gy * WD + gx;
        float s = 0.f;
#pragma unroll
        for (int c = 0; c < FPG; c++) s += p[(size_t)c * H * WD];
        S[r * SW + (side ? (4 + WD) : 3)] = s;
    }
    __syncthreads();

    // ---- Phase 2: j (output channel within group) OUTER and rolled -> low regs
    const int c = tid;                       // output column
    const float* Sc = S + c + 3;             // window base: cols c-1,c,c+1 -> Sc[0..2]
    float* outb = out + (((size_t)(bb * OUT_CH + g * FPG)) * H + y0) * WD + c;

#pragma unroll 1
    for (int j = 0; j < FPG; j++) {
        const float* w = &wk[j * 9];
        float w0 = w[0], w1 = w[1], w2 = w[2];
        float w3 = w[3], w4 = w[4], w5 = w[5];
        float w6 = w[6], w7 = w[7], w8 = w[8];

        float a0 = Sc[0],  a1 = Sc[1],      a2 = Sc[2];
        float b0 = Sc[SW], b1 = Sc[SW + 1], b2 = Sc[SW + 2];

        float* op = outb + (size_t)j * H * WD;
#pragma unroll 4
        for (int y = 0; y < TY; y++) {
            const float* rc = Sc + (y + 2) * SW;
            float c0 = rc[0], c1 = rc[1], c2 = rc[2];
            float acc;
            acc = w0 * a0;
            acc = fmaf(w1, a1, acc);
            acc = fmaf(w2, a2, acc);
            acc = fmaf(w3, b0, acc);
            acc = fmaf(w4, b1, acc);
            acc = fmaf(w5, b2, acc);
            acc = fmaf(w6, c0, acc);
            acc = fmaf(w7, c1, acc);
            acc = fmaf(w8, c2, acc);
            op[(size_t)y * WD] = acc;
            a0 = b0; a1 = b1; a2 = b2;
            b0 = c0; b1 = c1; b2 = c2;
        }
    }
}

extern "C" void kernel_launch(void* const* d_in, const int* in_sizes, int n_in,
                              void* d_out, int out_size) {
    const float* x   = (const float*)d_in[0];  // [8,64,256,256]
    const float* rep = (const float*)d_in[1];  // [8,32]
    const float* Wm  = (const float*)d_in[2];  // [576,32]
    float* out = (float*)d_out;                // [8,64,256,256]

    prep_weights<<<(NB * OUT_CH * KS * KS + 127) / 128, 128>>>(rep, Wm);
    dynconv<<<dim3(H / TY, GROUPS, NB), 256>>>(x, out);
}

// round 3
// speedup vs baseline: 1.5520x; 1.1285x over previous
#include <cuda_runtime.h>

#define NB     8
#define IN_CH  64
#define OUT_CH 64
#define GROUPS 8
#define FPG    8
#define H      256
#define WD     256
#define TY     16
#define SW     264        // smem row stride (floats); 264*4 bytes % 16 == 0

struct R6 { float v[6]; };

__device__ __forceinline__ R6 ldrow(const float* base) {
    // base points at S + r*SW + c0 ; window cols c0-1 .. c0+4 live at [3..8]
    R6 r;
    r.v[0] = base[3];
    float4 m = *(const float4*)(base + 4);
    r.v[1] = m.x; r.v[2] = m.y; r.v[3] = m.z; r.v[4] = m.w;
    r.v[5] = base[8];
    return r;
}

__device__ __forceinline__ void accum(float4& a, const R6& r,
                                      float w0, float w1, float w2) {
    a.x = fmaf(w0, r.v[0], a.x); a.x = fmaf(w1, r.v[1], a.x); a.x = fmaf(w2, r.v[2], a.x);
    a.y = fmaf(w0, r.v[1], a.y); a.y = fmaf(w1, r.v[2], a.y); a.y = fmaf(w2, r.v[3], a.y);
    a.z = fmaf(w0, r.v[2], a.z); a.z = fmaf(w1, r.v[3], a.z); a.z = fmaf(w2, r.v[4], a.z);
    a.w = fmaf(w0, r.v[3], a.w); a.w = fmaf(w1, r.v[4], a.w); a.w = fmaf(w2, r.v[5], a.w);
}

__global__ __launch_bounds__(256)
void dynconv(const float* __restrict__ x,
             const float* __restrict__ rep,
             const float* __restrict__ Wm,
             float* __restrict__ out) {
    __shared__ __align__(16) float S[(TY + 2) * SW];
    __shared__ float wk[FPG * 9];

    const int tid = threadIdx.x;
    const int y0  = blockIdx.x * TY;
    const int g   = blockIdx.y;
    const int bb  = blockIdx.z;

    // ---- Fused tap computation: leaky_relu(rep[bb] . W[g*72 + tid])
    if (tid < FPG * 9) {
        const float4* r4 = (const float4*)(rep + bb * 32);
        const float4* w4 = (const float4*)(Wm + (size_t)(g * 72 + tid) * 32);
        float acc = 0.f;
#pragma unroll
        for (int i = 0; i < 8; i++) {
            float4 a = r4[i], b = w4[i];
            acc = fmaf(a.x, b.x, acc); acc = fmaf(a.y, b.y, acc);
            acc = fmaf(a.z, b.z, acc); acc = fmaf(a.w, b.w, acc);
        }
        wk[tid] = acc >= 0.f ? acc : 0.1f * acc;
    }

    const float* xg = x + ((size_t)(bb * IN_CH + g * FPG)) * H * WD;

    // ---- Phase 1a: interior group-sum, float4
    for (int idx = tid; idx < (TY + 2) * (WD / 4); idx += 256) {
        int r = idx >> 6, q = idx & 63;
        int gy = y0 + r - 1;
        gy = gy < 0 ? -gy : (gy >= H ? 2 * H - 2 - gy : gy);
        const float4* p = (const float4*)(xg + (size_t)gy * WD) + q;
        float4 s = p[0];
#pragma unroll
        for (int c = 1; c < FPG; c++) {
            float4 v = p[(size_t)c * (H * WD / 4)];
            s.x += v.x; s.y += v.y; s.z += v.z; s.w += v.w;
        }
        *(float4*)&S[r * SW + 4 + 4 * q] = s;
    }
    // ---- Phase 1b: reflected halo columns (gx=-1 -> 1, gx=256 -> 254)
    if (tid < 2 * (TY + 2)) {
        int r = tid >> 1, side = tid & 1;
        int gy = y0 + r - 1;
        gy = gy < 0 ? -gy : (gy >= H ? 2 * H - 2 - gy : gy);
        int gx = side ? (WD - 2) : 1;
        const float* p = xg + (size_t)gy * WD + gx;
        float s = 0.f;
#pragma unroll
        for (int c = 0; c < FPG; c++) s += p[(size_t)c * H * WD];
        S[r * SW + (side ? (4 + WD) : 3)] = s;
    }
    __syncthreads();

    // ---- Phase 2: thread = (ry, qc) owns 4 cols x 4 rows per output channel j
    const int qc = tid & 63;       // column quad 0..63
    const int ry = tid >> 6;       // row slice 0..3
    const int c0 = qc * 4;
    const int ys = ry * 4;         // first output row (within tile)

    const float* Srow = S + ys * SW + c0;
    float* outb = out + (((size_t)(bb * OUT_CH + g * FPG)) * H + y0 + ys) * WD + c0;

#pragma unroll 1
    for (int j = 0; j < FPG; j++) {
        const float* w = &wk[j * 9];
        float w0 = w[0], w1 = w[1], w2 = w[2];
        float w3 = w[3], w4 = w[4], w5 = w[5];
        float w6 = w[6], w7 = w[7], w8 = w[8];

        R6 A = ldrow(Srow);
        R6 Bw = ldrow(Srow + SW);
        float* op = outb + (size_t)j * H * WD;

#pragma unroll
        for (int yy = 0; yy < 4; yy++) {
            R6 Cw = ldrow(Srow + (yy + 2) * SW);
            float4 acc = {0.f, 0.f, 0.f, 0.f};
            accum(acc, A,  w0, w1, w2);
            accum(acc, Bw, w3, w4, w5);
            accum(acc, Cw, w6, w7, w8);
            *(float4*)(op + (size_t)yy * WD) = acc;
            A = Bw; Bw = Cw;
        }
    }
}

extern "C" void kernel_launch(void* const* d_in, const int* in_sizes, int n_in,
                              void* d_out, int out_size) {
    const float* x   = (const float*)d_in[0];  // [8,64,256,256]
    const float* rep = (const float*)d_in[1];  // [8,32]
    const float* Wm  = (const float*)d_in[2];  // [576,32]
    float* out = (float*)d_out;                // [8,64,256,256]

    dynconv<<<dim3(H / TY, GROUPS, NB), 256>>>(x, rep, Wm, out);
}